// round 13
// baseline (speedup 1.0000x reference)
#include <cuda_runtime.h>
#include <cuda_fp16.h>
#include <math.h>
#include <stdint.h>

// ===========================================================================
// StreamingSSMCell (B=8192, D=1024, DCONV=4) — fp16 m16n8k8 GEMM + fusion
//   m16n8k16 f16 was pathological on sm_103 (R6); k8 uses the identical
//   fragment layout (two k8 = one k16 fragment pair) and may run at the
//   native fp16 HMMA rate (2x tf32). Keep R11's proven fusion:
//   G1 computes interleaved (x_inner,z) pairs, epilogue does conv/decay/gate
//   and writes h_new, new_buf, g(fp16). G2: out = g @ W_out^T + b_out.
//   d_out layout: [ out (B*D) | h_new (B*D) | new_buf (B*D*4) ]
// ===========================================================================

#define D_MODEL 1024
#define BATCH   8192

__device__ __half g_gh [(size_t)BATCH * D_MODEL];    // gated act (fp16)
__device__ __half g_xh [(size_t)BATCH * D_MODEL];    // x fp16
__device__ __half g_wih[(size_t)2 * D_MODEL * D_MODEL]; // W_in fp16
__device__ __half g_woh[(size_t)D_MODEL * D_MODEL];  // W_out fp16

// ------------------------------ GEMM config --------------------------------
#define NTHREADS 512                 // 16 warps: wm(2) x wn(8), 64x32 each
#define BK 32                        // halves per k-tile (64 B of data/row)
#define ROW_B 80                     // padded row bytes (40 halves)
#define ATILE_B (128 * ROW_B)        // 10240 B  (A: 128 rows)
#define BTILE_B (256 * ROW_B)        // 20480 B  (B: 256 rows)
#define STAGE_B (ATILE_B + BTILE_B)  // 30720 B
#define NSTAGE  3
#define SMEM_BYTES (NSTAGE * STAGE_B)   // 92160 B

// ------------------------------ PTX helpers --------------------------------
__device__ __forceinline__ uint32_t smem_u32(const void* p) {
    uint32_t a;
    asm("{ .reg .u64 t; cvta.to.shared.u64 t, %1; cvt.u32.u64 %0, t; }"
        : "=r"(a) : "l"(p));
    return a;
}

#define CP_ASYNC16(dst, src) \
    asm volatile("cp.async.cg.shared.global [%0], [%1], 16;" :: "r"(dst), "l"(src))
#define CP_ASYNC_COMMIT() asm volatile("cp.async.commit_group;" ::: "memory")
#define CP_ASYNC_WAIT1()  asm volatile("cp.async.wait_group 1;" ::: "memory")

#define LDSM_X4(r0, r1, r2, r3, addr)                                          \
    asm volatile("ldmatrix.sync.aligned.m8n8.x4.shared.b16 {%0,%1,%2,%3}, [%4];" \
        : "=r"(r0), "=r"(r1), "=r"(r2), "=r"(r3) : "r"(addr))

// fp16 k8 MMA: A {a0,a1} (16x8), B {b0} (8x8), C f32 {c0..c3}
#define MMA_F16_K8(c, a0, a1, b0)                                              \
    asm volatile("mma.sync.aligned.m16n8k8.row.col.f32.f16.f16.f32 "           \
        "{%0,%1,%2,%3}, {%4,%5}, {%6}, {%0,%1,%2,%3};"                         \
        : "+f"((c)[0]), "+f"((c)[1]), "+f"((c)[2]), "+f"((c)[3])               \
        : "r"(a0), "r"(a1), "r"(b0))

__device__ __forceinline__ float silu_f(float x) {
    return __fdividef(x, 1.0f + __expf(-x));
}

// ====================== GEMM1 + fused elementwise ===========================
// A = x_h [B, D] fp16; B tile row r <- W_in_h row (r&1)*D + n0d + (r>>1).
// grid = (D/128, B/128), 512 threads. Epilogue writes h_new, new_buf, g(fp16).
__global__ __launch_bounds__(NTHREADS, 1)
void gemm1_fused_f16(const __half* __restrict__ A,      // x fp16 [B, D]
                     const __half* __restrict__ Bm,     // W_in fp16 [2D, D]
                     const float* __restrict__ b_in,    // [2D]
                     const float* __restrict__ h,       // [B, D]
                     const float* __restrict__ conv_buf,// [B, D, 4]
                     const float* __restrict__ conv_w,  // [D, 4]
                     const float* __restrict__ conv_b,  // [D]
                     float* __restrict__ out_hnew,      // [B, D]
                     float* __restrict__ out_newbuf,    // [B, D, 4]
                     __half* __restrict__ g_out)        // [B, D] fp16
{
    extern __shared__ char smem[];
    const uint32_t sbase = smem_u32(smem);
    const int tid  = threadIdx.x;
    const int lane = tid & 31;
    const int wid  = tid >> 5;
    const int wm = wid >> 3;             // 0..1
    const int wn = wid & 7;              // 0..7
    const int g  = lane >> 2;
    const int tg = lane & 3;
    const int m0  = blockIdx.y * 128;
    const int n0d = blockIdx.x * 128;    // 128 d's (256 interleaved cols)
    const int T = D_MODEL / BK;          // 32

    uint32_t a_off[4];
    #pragma unroll
    for (int i = 0; i < 4; i++) {
        const int row = wm * 64 + i * 16 + (lane & 15);
        a_off[i] = (uint32_t)(row * ROW_B + (lane >> 4) * 16);
    }
    uint32_t b_off[2];
    #pragma unroll
    for (int jj = 0; jj < 2; jj++) {
        const int row = wn * 32 + jj * 16 + ((lane >> 4) << 3) + (lane & 7);
        b_off[jj] = (uint32_t)(ATILE_B + row * ROW_B + ((lane >> 3) & 1) * 16);
    }

    float acc[4][4][4];
    #pragma unroll
    for (int i = 0; i < 4; i++)
        #pragma unroll
        for (int j = 0; j < 4; j++)
            #pragma unroll
            for (int r = 0; r < 4; r++) acc[i][j][r] = 0.0f;

    // loader: A 512 chunks (1/thread), B 1024 chunks (2/thread); chunk = 8 halves
    #define LOAD1(t) do {                                                      \
        const uint32_t _s = sbase + ((t) % NSTAGE) * STAGE_B;                  \
        {                                                                      \
            const int _r = tid >> 2, _c = tid & 3;                             \
            CP_ASYNC16(_s + (uint32_t)(_r * ROW_B + _c * 16),                  \
                       A + (size_t)(m0 + _r) * D_MODEL + (size_t)(t) * BK + _c * 8); \
        }                                                                      \
        _Pragma("unroll")                                                      \
        for (int _q = 0; _q < 2; _q++) {                                       \
            const int _id = tid + _q * NTHREADS;                               \
            const int _r = _id >> 2, _c = _id & 3;                             \
            const int _grow = ((_r & 1) ? D_MODEL : 0) + n0d + (_r >> 1);      \
            CP_ASYNC16(_s + (uint32_t)(ATILE_B + _r * ROW_B + _c * 16),        \
                       Bm + (size_t)_grow * D_MODEL + (size_t)(t) * BK + _c * 8); \
        }                                                                      \
        CP_ASYNC_COMMIT();                                                     \
    } while (0)

    LOAD1(0);
    LOAD1(1);

    for (int t = 0; t < T; t++) {
        CP_ASYNC_WAIT1();
        __syncthreads();

        if (t + 2 < T) { LOAD1(t + 2); } else { CP_ASYNC_COMMIT(); }

        const uint32_t st = sbase + (t % NSTAGE) * STAGE_B;

        #pragma unroll
        for (int ks = 0; ks < 2; ks++) {         // two k16 fragment groups
            const uint32_t kb = (uint32_t)(ks * 32);   // 16 halves = 32 B
            uint32_t af[4][4], bf[4][2];
            #pragma unroll
            for (int i = 0; i < 4; i++)
                LDSM_X4(af[i][0], af[i][1], af[i][2], af[i][3],
                        st + a_off[i] + kb);
            #pragma unroll
            for (int jj = 0; jj < 2; jj++)
                LDSM_X4(bf[2 * jj][0], bf[2 * jj][1],
                        bf[2 * jj + 1][0], bf[2 * jj + 1][1],
                        st + b_off[jj] + kb);
            #pragma unroll
            for (int i = 0; i < 4; i++)
                #pragma unroll
                for (int j = 0; j < 4; j++) {
                    MMA_F16_K8(acc[i][j], af[i][0], af[i][1], bf[j][0]);
                    MMA_F16_K8(acc[i][j], af[i][2], af[i][3], bf[j][1]);
                }
        }
    }
    #undef LOAD1

    // ---------------- fused elementwise epilogue ----------------
    #pragma unroll
    for (int j = 0; j < 4; j++) {
        const int d = n0d + wn * 16 + j * 4 + tg;
        const float bi  = b_in[d];
        const float biz = b_in[D_MODEL + d];
        const float4 cw = *(const float4*)(conv_w + (size_t)d * 4);
        const float cbv = conv_b[d];
        const float tt = 2.302585092994046f
                       + (float)d * (7.600902459542082f - 2.302585092994046f)
                         / (float)(D_MODEL - 1);
        const float dec = __expf(-__expf(-tt));

        #pragma unroll
        for (int i = 0; i < 4; i++) {
            #pragma unroll
            for (int e = 0; e < 2; e++) {
                const int row = m0 + wm * 64 + i * 16 + g + e * 8;
                const size_t idx = (size_t)row * D_MODEL + d;

                const float xi = acc[i][j][e * 2 + 0] + bi;
                const float zz = acc[i][j][e * 2 + 1] + biz;

                const float4 cb = *(const float4*)(conv_buf + idx * 4);
                float co = cb.y * cw.x + cb.z * cw.y + cb.w * cw.z
                         + xi * cw.w + cbv;
                co = silu_f(co);

                const float hn = dec * h[idx] + (1.0f - dec) * co;

                out_hnew[idx] = hn;
                float4 nb; nb.x = cb.y; nb.y = cb.z; nb.z = cb.w; nb.w = xi;
                *(float4*)(out_newbuf + idx * 4) = nb;
                g_out[idx] = __float2half_rn(hn * silu_f(zz));
            }
        }
    }
}

// ========================= GEMM2: fp16 k8 ====================================
// C[m,n] = sum_k A[m,k]*Bm[n,k] + bias[n]; A, Bm fp16 K-major.
// grid = (N/256, M/128), 512 threads.
__global__ __launch_bounds__(NTHREADS, 1)
void gemm2_f16(const __half* __restrict__ A, int lda,
               const __half* __restrict__ Bm, int ldb,
               const float* __restrict__ bias,
               float* __restrict__ C, int ldc, int K)
{
    extern __shared__ char smem[];
    const uint32_t sbase = smem_u32(smem);
    const int tid  = threadIdx.x;
    const int lane = tid & 31;
    const int wid  = tid >> 5;
    const int wm = wid >> 3;
    const int wn = wid & 7;
    const int g  = lane >> 2;
    const int tg = lane & 3;
    const int m0 = blockIdx.y * 128;
    const int n0 = blockIdx.x * 256;
    const int T = K / BK;

    uint32_t a_off[4];
    #pragma unroll
    for (int i = 0; i < 4; i++) {
        const int row = wm * 64 + i * 16 + (lane & 15);
        a_off[i] = (uint32_t)(row * ROW_B + (lane >> 4) * 16);
    }
    uint32_t b_off[2];
    #pragma unroll
    for (int jj = 0; jj < 2; jj++) {
        const int row = wn * 32 + jj * 16 + ((lane >> 4) << 3) + (lane & 7);
        b_off[jj] = (uint32_t)(ATILE_B + row * ROW_B + ((lane >> 3) & 1) * 16);
    }

    float acc[4][4][4];
    #pragma unroll
    for (int i = 0; i < 4; i++)
        #pragma unroll
        for (int j = 0; j < 4; j++)
            #pragma unroll
            for (int r = 0; r < 4; r++) acc[i][j][r] = 0.0f;

    #define LOAD2(t) do {                                                      \
        const uint32_t _s = sbase + ((t) % NSTAGE) * STAGE_B;                  \
        {                                                                      \
            const int _r = tid >> 2, _c = tid & 3;                             \
            CP_ASYNC16(_s + (uint32_t)(_r * ROW_B + _c * 16),                  \
                       A + (size_t)(m0 + _r) * lda + (size_t)(t) * BK + _c * 8); \
        }                                                                      \
        _Pragma("unroll")                                                      \
        for (int _q = 0; _q < 2; _q++) {                                       \
            const int _id = tid + _q * NTHREADS;                               \
            const int _r = _id >> 2, _c = _id & 3;                             \
            CP_ASYNC16(_s + (uint32_t)(ATILE_B + _r * ROW_B + _c * 16),        \
                       Bm + (size_t)(n0 + _r) * ldb + (size_t)(t) * BK + _c * 8); \
        }                                                                      \
        CP_ASYNC_COMMIT();                                                     \
    } while (0)

    LOAD2(0);
    LOAD2(1);

    for (int t = 0; t < T; t++) {
        CP_ASYNC_WAIT1();
        __syncthreads();

        if (t + 2 < T) { LOAD2(t + 2); } else { CP_ASYNC_COMMIT(); }

        const uint32_t st = sbase + (t % NSTAGE) * STAGE_B;

        #pragma unroll
        for (int ks = 0; ks < 2; ks++) {
            const uint32_t kb = (uint32_t)(ks * 32);
            uint32_t af[4][4], bf[4][2];
            #pragma unroll
            for (int i = 0; i < 4; i++)
                LDSM_X4(af[i][0], af[i][1], af[i][2], af[i][3],
                        st + a_off[i] + kb);
            #pragma unroll
            for (int jj = 0; jj < 2; jj++)
                LDSM_X4(bf[2 * jj][0], bf[2 * jj][1],
                        bf[2 * jj + 1][0], bf[2 * jj + 1][1],
                        st + b_off[jj] + kb);
            #pragma unroll
            for (int i = 0; i < 4; i++)
                #pragma unroll
                for (int j = 0; j < 4; j++) {
                    MMA_F16_K8(acc[i][j], af[i][0], af[i][1], bf[j][0]);
                    MMA_F16_K8(acc[i][j], af[i][2], af[i][3], bf[j][1]);
                }
        }
    }
    #undef LOAD2

    #pragma unroll
    for (int j = 0; j < 4; j++) {
        const int col = n0 + wn * 32 + j * 8 + tg * 2;
        const float2 bb = *(const float2*)(bias + col);
        #pragma unroll
        for (int i = 0; i < 4; i++) {
            const int r0 = m0 + wm * 64 + i * 16 + g;
            float2 v0; v0.x = acc[i][j][0] + bb.x; v0.y = acc[i][j][1] + bb.y;
            *(float2*)(C + (size_t)r0 * ldc + col) = v0;
            float2 v1; v1.x = acc[i][j][2] + bb.x; v1.y = acc[i][j][3] + bb.y;
            *(float2*)(C + (size_t)(r0 + 8) * ldc + col) = v1;
        }
    }
}

// --------------------------- fp32 -> fp16 convert ---------------------------
__global__ void f2h_kernel(const float* __restrict__ in,
                           __half* __restrict__ out, int n8)
{
    const int i = blockIdx.x * blockDim.x + threadIdx.x;
    if (i >= n8) return;
    const float4 v0 = ((const float4*)in)[2 * i];
    const float4 v1 = ((const float4*)in)[2 * i + 1];
    __half2 hh[4];
    hh[0] = __floats2half2_rn(v0.x, v0.y);
    hh[1] = __floats2half2_rn(v0.z, v0.w);
    hh[2] = __floats2half2_rn(v1.x, v1.y);
    hh[3] = __floats2half2_rn(v1.z, v1.w);
    ((uint4*)out)[i] = *(const uint4*)hh;
}

// ------------------------------- launch ------------------------------------
extern "C" void kernel_launch(void* const* d_in, const int* in_sizes, int n_in,
                              void* d_out, int out_size)
{
    const float* x        = (const float*)d_in[0];
    const float* h        = (const float*)d_in[1];
    const float* conv_buf = (const float*)d_in[2];
    const float* W_in     = (const float*)d_in[3];
    const float* b_in     = (const float*)d_in[4];
    const float* conv_w   = (const float*)d_in[5];
    const float* conv_b   = (const float*)d_in[6];
    const float* W_out    = (const float*)d_in[7];
    const float* b_out    = (const float*)d_in[8];

    const int D = in_sizes[6];
    const int B = in_sizes[0] / D;
    const int twoD = in_sizes[4];

    float* out      = (float*)d_out;
    float* out_hnew = out + (size_t)B * D;
    float* out_nbuf = out + (size_t)2 * B * D;

    cudaFuncSetAttribute(gemm1_fused_f16,
                         cudaFuncAttributeMaxDynamicSharedMemorySize, SMEM_BYTES);
    cudaFuncSetAttribute(gemm2_f16,
                         cudaFuncAttributeMaxDynamicSharedMemorySize, SMEM_BYTES);

    // converts (cheap, bandwidth-bound)
    {
        int n8 = B * D / 8;
        f2h_kernel<<<(n8 + 255) / 256, 256>>>(x, g_xh, n8);
        n8 = twoD * D / 8;
        f2h_kernel<<<(n8 + 255) / 256, 256>>>(W_in, g_wih, n8);
        n8 = D * D / 8;
        f2h_kernel<<<(n8 + 255) / 256, 256>>>(W_out, g_woh, n8);
    }

    // GEMM1 + fused elementwise: writes h_new, new_buf, g (fp16)
    {
        dim3 grid(D / 128, B / 128);     // (8, 64)
        gemm1_fused_f16<<<grid, NTHREADS, SMEM_BYTES>>>(
            g_xh, g_wih, b_in, h, conv_buf, conv_w, conv_b,
            out_hnew, out_nbuf, g_gh);
    }

    // GEMM2: out = g @ W_out^T + b_out  [B, D]
    {
        dim3 grid(D / 256, B / 128);     // (4, 64)
        gemm2_f16<<<grid, NTHREADS, SMEM_BYTES>>>(g_gh, D, g_woh, D, b_out,
                                                  out, D, D);
    }
}

// round 14
// speedup vs baseline: 11.2727x; 11.2727x over previous
#include <cuda_runtime.h>
#include <math.h>
#include <stdint.h>

// ===========================================================================
// StreamingSSMCell (B=8192, D=1024, DCONV=4) — persistent fused pipeline
//   ONE persistent kernel (148 CTAs = 1/SM), work queue:
//     items [0,512):   G1 tiles — xz-pair GEMM + fused conv/decay/gate epilogue
//     items [512,768): G2 tiles — out = g @ W_out^T + b_out
//   G2 tile (m) spins on g_ctr[m] (8 G1 tiles per m-row-block) -> G1 tail
//   and the inter-kernel barrier overlap with G2 work.
//   d_out layout: [ out (B*D) | h_new (B*D) | new_buf (B*D*4) ]
// ===========================================================================

#define D_MODEL 1024
#define BATCH   8192
#define NSM     148

__device__ float g_g[(size_t)BATCH * D_MODEL];   // gated activation
__device__ int   g_ctr[BATCH / 128];             // per-m-row-block G1 counters

// ------------------------------ GEMM config --------------------------------
#define BM 128
#define BN 256
#define BK 32
#define KPAD 36
#define NTHREADS 512
#define NSTAGE 3
#define A_TILE_WORDS (BM * KPAD)
#define B_TILE_WORDS (BN * KPAD)
#define STAGE_WORDS  (A_TILE_WORDS + B_TILE_WORDS)
#define SMEM_BYTES   (NSTAGE * STAGE_WORDS * 4)      // 165888

// ------------------------------ PTX helpers --------------------------------
__device__ __forceinline__ uint32_t smem_u32(const void* p) {
    uint32_t a;
    asm("{ .reg .u64 t; cvta.to.shared.u64 t, %1; cvt.u32.u64 %0, t; }"
        : "=r"(a) : "l"(p));
    return a;
}

#define CP_ASYNC16(dst, src) \
    asm volatile("cp.async.cg.shared.global [%0], [%1], 16;" :: "r"(dst), "l"(src))
#define CP_ASYNC_COMMIT()   asm volatile("cp.async.commit_group;" ::: "memory")
#define CP_ASYNC_WAIT1()    asm volatile("cp.async.wait_group 1;" ::: "memory")
#define CP_ASYNC_WAIT_ALL() asm volatile("cp.async.wait_group 0;" ::: "memory")

__device__ __forceinline__ uint32_t rna(uint32_t x) {
    uint32_t r;
    asm("cvt.rna.tf32.f32 %0, %1;" : "=r"(r) : "f"(__uint_as_float(x)));
    return r;
}

#define LDSM_X4(r0, r1, r2, r3, addr)                                          \
    asm volatile("ldmatrix.sync.aligned.m8n8.x4.shared.b16 {%0,%1,%2,%3}, [%4];" \
        : "=r"(r0), "=r"(r1), "=r"(r2), "=r"(r3) : "r"(addr))

#define MMA_TF32(c, a, b)                                                      \
    asm volatile("mma.sync.aligned.m16n8k8.row.col.f32.tf32.tf32.f32 "         \
        "{%0,%1,%2,%3}, {%4,%5,%6,%7}, {%8,%9}, {%0,%1,%2,%3};"                \
        : "+f"((c)[0]), "+f"((c)[1]), "+f"((c)[2]), "+f"((c)[3])               \
        : "r"((a)[0]), "r"((a)[1]), "r"((a)[2]), "r"((a)[3]),                  \
          "r"((b)[0]), "r"((b)[1]))

__device__ __forceinline__ float silu_f(float x) {
    return __fdividef(x, 1.0f + __expf(-x));
}

// --------------------------- counter zero kernel ----------------------------
__global__ void zero_ctr(int n) {
    if (threadIdx.x < n) g_ctr[threadIdx.x] = 0;
}

// =========================== persistent pipeline ============================
__global__ __launch_bounds__(NTHREADS, 1)
void ssm_persistent(const float* __restrict__ x,        // [B, D]
                    const float* __restrict__ W_in,     // [2D, D]
                    const float* __restrict__ b_in,     // [2D]
                    const float* __restrict__ h,        // [B, D]
                    const float* __restrict__ conv_buf, // [B, D, 4]
                    const float* __restrict__ conv_w,   // [D, 4]
                    const float* __restrict__ conv_b,   // [D]
                    const float* __restrict__ W_out,    // [D, D]
                    const float* __restrict__ b_out,    // [D]
                    float* __restrict__ out,            // [B, D]
                    float* __restrict__ out_hnew,       // [B, D]
                    float* __restrict__ out_newbuf)     // [B, D, 4]
{
    extern __shared__ float smem[];
    const uint32_t sbase = smem_u32(smem);
    const int tid  = threadIdx.x;
    const int lane = tid & 31;
    const int wid  = tid >> 5;
    const int wm = wid >> 3;             // 0..1
    const int wn = wid & 7;              // 0..7
    const int g  = lane >> 2;
    const int tg = lane & 3;
    const int T = D_MODEL / BK;          // 32

    // ldmatrix byte offsets (same smem layout for both item kinds)
    uint32_t a_off[4];
    #pragma unroll
    for (int i = 0; i < 4; i++) {
        const int row = wm * 64 + i * 16 + (lane & 15);
        a_off[i] = (uint32_t)(row * KPAD + ((lane >> 4) << 2)) * 4u;
    }
    uint32_t b_off[2];
    #pragma unroll
    for (int jj = 0; jj < 2; jj++) {
        const int row = wn * 32 + jj * 16 + ((lane >> 4) << 3) + (lane & 7);
        b_off[jj] = (uint32_t)(row * KPAD + (((lane >> 3) & 1) << 2)) * 4u
                    + (uint32_t)(A_TILE_WORDS * 4);
    }

    const int mT  = BATCH / 128;         // 64
    const int nG1 = mT * (D_MODEL / 128);      // 512
    const int nG2 = mT * (D_MODEL / 256);      // 256
    const int nItems = nG1 + nG2;              // 768

    for (int item = blockIdx.x; item < nItems; item += NSM) {
        // drain previous item's async pipe + smem reads before reuse
        CP_ASYNC_WAIT_ALL();
        __syncthreads();

        float acc[4][4][4];
        #pragma unroll
        for (int i = 0; i < 4; i++)
            #pragma unroll
            for (int j = 0; j < 4; j++)
                #pragma unroll
                for (int r = 0; r < 4; r++) acc[i][j][r] = 0.0f;

        if (item < nG1) {
            // ================= G1 tile: xz pairs + fused epilogue ===========
            const int mt  = item >> 3;
            const int m0  = mt * 128;
            const int n0d = (item & 7) * 128;

            #define LOAD1(t) do {                                              \
                const uint32_t _s = sbase + ((t) % NSTAGE) * (STAGE_WORDS * 4);\
                _Pragma("unroll")                                              \
                for (int _q = 0; _q < 2; _q++) {                               \
                    const int _id = tid + _q * NTHREADS;                       \
                    const int _r = _id >> 3, _c = _id & 7;                     \
                    CP_ASYNC16(_s + _r * (KPAD * 4) + _c * 16,                 \
                        x + (size_t)(m0 + _r) * D_MODEL + (size_t)(t) * BK + _c * 4); \
                }                                                              \
                const uint32_t _sb = _s + A_TILE_WORDS * 4;                    \
                _Pragma("unroll")                                              \
                for (int _q = 0; _q < 4; _q++) {                               \
                    const int _id = tid + _q * NTHREADS;                       \
                    const int _r = _id >> 3, _c = _id & 7;                     \
                    const int _grow = ((_id & 8) ? D_MODEL : 0) + n0d + (_r >> 1); \
                    CP_ASYNC16(_sb + _r * (KPAD * 4) + _c * 16,                \
                        W_in + (size_t)_grow * D_MODEL + (size_t)(t) * BK + _c * 4); \
                }                                                              \
                CP_ASYNC_COMMIT();                                             \
            } while (0)

            LOAD1(0);
            LOAD1(1);

            for (int t = 0; t < T; t++) {
                CP_ASYNC_WAIT1();
                __syncthreads();
                if (t + 2 < T) { LOAD1(t + 2); } else { CP_ASYNC_COMMIT(); }

                const uint32_t st = sbase + (t % NSTAGE) * (STAGE_WORDS * 4);
                #pragma unroll
                for (int k0 = 0; k0 < BK; k0 += 8) {
                    const uint32_t kb = (uint32_t)(k0 * 4);
                    uint32_t af[4][4], bf[4][2];
                    #pragma unroll
                    for (int i = 0; i < 4; i++)
                        LDSM_X4(af[i][0], af[i][1], af[i][2], af[i][3],
                                st + a_off[i] + kb);
                    #pragma unroll
                    for (int jj = 0; jj < 2; jj++)
                        LDSM_X4(bf[jj * 2][0], bf[jj * 2][1],
                                bf[jj * 2 + 1][0], bf[jj * 2 + 1][1],
                                st + b_off[jj] + kb);
                    #pragma unroll
                    for (int i = 0; i < 4; i++)
                        #pragma unroll
                        for (int q = 0; q < 4; q++) af[i][q] = rna(af[i][q]);
                    #pragma unroll
                    for (int j = 0; j < 4; j++) {
                        bf[j][0] = rna(bf[j][0]);
                        bf[j][1] = rna(bf[j][1]);
                    }
                    #pragma unroll
                    for (int i = 0; i < 4; i++)
                        #pragma unroll
                        for (int j = 0; j < 4; j++)
                            MMA_TF32(acc[i][j], af[i], bf[j]);
                }
            }
            #undef LOAD1

            // fused elementwise epilogue
            #pragma unroll
            for (int j = 0; j < 4; j++) {
                const int d = n0d + wn * 16 + j * 4 + tg;
                const float bi  = b_in[d];
                const float biz = b_in[D_MODEL + d];
                const float4 cw = *(const float4*)(conv_w + (size_t)d * 4);
                const float cbv = conv_b[d];
                const float tt = 2.302585092994046f
                               + (float)d * (7.600902459542082f - 2.302585092994046f)
                                 / (float)(D_MODEL - 1);
                const float dec = __expf(-__expf(-tt));

                #pragma unroll
                for (int i = 0; i < 4; i++) {
                    #pragma unroll
                    for (int e = 0; e < 2; e++) {
                        const int row = m0 + wm * 64 + i * 16 + g + e * 8;
                        const size_t idx = (size_t)row * D_MODEL + d;

                        const float xi = acc[i][j][e * 2 + 0] + bi;
                        const float zz = acc[i][j][e * 2 + 1] + biz;

                        const float4 cb = *(const float4*)(conv_buf + idx * 4);
                        float co = cb.y * cw.x + cb.z * cw.y + cb.w * cw.z
                                 + xi * cw.w + cbv;
                        co = silu_f(co);

                        const float hn = dec * h[idx] + (1.0f - dec) * co;

                        out_hnew[idx] = hn;
                        float4 nb;
                        nb.x = cb.y; nb.y = cb.z; nb.z = cb.w; nb.w = xi;
                        *(float4*)(out_newbuf + idx * 4) = nb;
                        g_g[idx] = hn * silu_f(zz);
                    }
                }
            }

            // signal this G1 tile complete for its m-row-block
            __syncthreads();
            if (tid == 0) {
                __threadfence();
                atomicAdd(&g_ctr[mt], 1);
            }
        } else {
            // ================= G2 tile: out = g @ W_out^T + b_out ===========
            const int r2 = item - nG1;
            const int mt = r2 >> 2;
            const int m0 = mt * 128;
            const int n0 = (r2 & 3) * 256;

            // wait until all 8 G1 tiles for this m-row-block are done
            if (tid == 0) {
                while (atomicAdd(&g_ctr[mt], 0) < 8) { __nanosleep(200); }
                __threadfence();
            }
            __syncthreads();

            #define LOAD2(t) do {                                              \
                const uint32_t _s = sbase + ((t) % NSTAGE) * (STAGE_WORDS * 4);\
                _Pragma("unroll")                                              \
                for (int _q = 0; _q < 2; _q++) {                               \
                    const int _id = tid + _q * NTHREADS;                       \
                    const int _r = _id >> 3, _c = _id & 7;                     \
                    CP_ASYNC16(_s + _r * (KPAD * 4) + _c * 16,                 \
                        g_g + (size_t)(m0 + _r) * D_MODEL + (size_t)(t) * BK + _c * 4); \
                }                                                              \
                const uint32_t _sb = _s + A_TILE_WORDS * 4;                    \
                _Pragma("unroll")                                              \
                for (int _q = 0; _q < 4; _q++) {                               \
                    const int _id = tid + _q * NTHREADS;                       \
                    const int _r = _id >> 3, _c = _id & 7;                     \
                    CP_ASYNC16(_sb + _r * (KPAD * 4) + _c * 16,                \
                        W_out + (size_t)(n0 + _r) * D_MODEL + (size_t)(t) * BK + _c * 4); \
                }                                                              \
                CP_ASYNC_COMMIT();                                             \
            } while (0)

            LOAD2(0);
            LOAD2(1);

            for (int t = 0; t < T; t++) {
                CP_ASYNC_WAIT1();
                __syncthreads();
                if (t + 2 < T) { LOAD2(t + 2); } else { CP_ASYNC_COMMIT(); }

                const uint32_t st = sbase + (t % NSTAGE) * (STAGE_WORDS * 4);
                #pragma unroll
                for (int k0 = 0; k0 < BK; k0 += 8) {
                    const uint32_t kb = (uint32_t)(k0 * 4);
                    uint32_t af[4][4], bf[4][2];
                    #pragma unroll
                    for (int i = 0; i < 4; i++)
                        LDSM_X4(af[i][0], af[i][1], af[i][2], af[i][3],
                                st + a_off[i] + kb);
                    #pragma unroll
                    for (int jj = 0; jj < 2; jj++)
                        LDSM_X4(bf[jj * 2][0], bf[jj * 2][1],
                                bf[jj * 2 + 1][0], bf[jj * 2 + 1][1],
                                st + b_off[jj] + kb);
                    #pragma unroll
                    for (int i = 0; i < 4; i++)
                        #pragma unroll
                        for (int q = 0; q < 4; q++) af[i][q] = rna(af[i][q]);
                    #pragma unroll
                    for (int j = 0; j < 4; j++) {
                        bf[j][0] = rna(bf[j][0]);
                        bf[j][1] = rna(bf[j][1]);
                    }
                    #pragma unroll
                    for (int i = 0; i < 4; i++)
                        #pragma unroll
                        for (int j = 0; j < 4; j++)
                            MMA_TF32(acc[i][j], af[i], bf[j]);
                }
            }
            #undef LOAD2

            // epilogue: add bias, store out
            #pragma unroll
            for (int j = 0; j < 4; j++) {
                const int col = n0 + wn * 32 + j * 8 + tg * 2;
                const float2 bb = *(const float2*)(b_out + col);
                #pragma unroll
                for (int i = 0; i < 4; i++) {
                    const int r0 = m0 + wm * 64 + i * 16 + g;
                    float2 v0;
                    v0.x = acc[i][j][0] + bb.x; v0.y = acc[i][j][1] + bb.y;
                    *(float2*)(out + (size_t)r0 * D_MODEL + col) = v0;
                    float2 v1;
                    v1.x = acc[i][j][2] + bb.x; v1.y = acc[i][j][3] + bb.y;
                    *(float2*)(out + (size_t)(r0 + 8) * D_MODEL + col) = v1;
                }
            }
        }
    }
}

// ------------------------------- launch ------------------------------------
extern "C" void kernel_launch(void* const* d_in, const int* in_sizes, int n_in,
                              void* d_out, int out_size)
{
    const float* x        = (const float*)d_in[0];
    const float* h        = (const float*)d_in[1];
    const float* conv_buf = (const float*)d_in[2];
    const float* W_in     = (const float*)d_in[3];
    const float* b_in     = (const float*)d_in[4];
    const float* conv_w   = (const float*)d_in[5];
    const float* conv_b   = (const float*)d_in[6];
    const float* W_out    = (const float*)d_in[7];
    const float* b_out    = (const float*)d_in[8];

    const int D = in_sizes[6];
    const int B = in_sizes[0] / D;

    float* out      = (float*)d_out;
    float* out_hnew = out + (size_t)B * D;
    float* out_nbuf = out + (size_t)2 * B * D;

    cudaFuncSetAttribute(ssm_persistent,
                         cudaFuncAttributeMaxDynamicSharedMemorySize, SMEM_BYTES);

    // zero the per-m-row-block counters (inside the graph, every replay)
    zero_ctr<<<1, 64>>>(B / 128);

    // one persistent kernel: G1 tiles then G2 tiles with dependency spin
    ssm_persistent<<<NSM, NTHREADS, SMEM_BYTES>>>(
        x, W_in, b_in, h, conv_buf, conv_w, conv_b, W_out, b_out,
        out, out_hnew, out_nbuf);
}